// round 2
// baseline (speedup 1.0000x reference)
#include <cuda_runtime.h>

#define N_NODES 20000
#define N_EDGES 640000
#define D 512

// ---------------- scratch (no allocs allowed) ----------------
__device__ float g_h0[N_NODES * D];   // layer input features
__device__ float g_msg[N_NODES * D];  // neighbor sum (scaled inside GEMM)
__device__ float g_h1[N_NODES * D];   // layer-1 output
__device__ float g_deg[N_NODES];      // degree -> 1/max(deg,1)

// ---------------- embedding lookup ----------------
__global__ void k_embed(const int* __restrict__ type,
                        const float* __restrict__ emb,
                        float* __restrict__ h) {
    int idx = blockIdx.x * blockDim.x + threadIdx.x;  // one float4 per thread
    int n = idx >> 7;              // 128 float4 per row (D=512)
    int j = (idx & 127) << 2;
    if (n < N_NODES) {
        int t = __ldg(&type[n]);
        float4 v = *reinterpret_cast<const float4*>(&emb[(size_t)t * D + j]);
        *reinterpret_cast<float4*>(&h[(size_t)n * D + j]) = v;
    }
}

// ---------------- degree ----------------
__global__ void k_deg(const int* __restrict__ dst, float* __restrict__ deg) {
    int e = blockIdx.x * blockDim.x + threadIdx.x;
    if (e < N_EDGES) atomicAdd(&deg[dst[e]], 1.0f);
}

__global__ void k_inv(float* __restrict__ deg) {
    int i = blockIdx.x * blockDim.x + threadIdx.x;
    if (i < N_NODES) deg[i] = 1.0f / fmaxf(deg[i], 1.0f);
}

// ---------------- edge scatter: msg[dst] += h[src] ----------------
// One warp handles 2 edges: 16 lanes per edge, 2 float4 (32 floats) per lane.
__global__ void k_scatter(const int* __restrict__ src, const int* __restrict__ dst,
                          const float* __restrict__ h, float* __restrict__ msg) {
    int warp = (blockIdx.x * blockDim.x + threadIdx.x) >> 5;
    int lane = threadIdx.x & 31;
    int e = warp * 2 + (lane >> 4);       // edge index
    int sub = lane & 15;                  // 16 lanes cover 64 float4? no: 128 floats = 32 float4
    if (e >= N_EDGES) return;
    int s = __ldg(&src[e]);
    int d = __ldg(&dst[e]);
    const float4* hs = reinterpret_cast<const float4*>(h + (size_t)s * D);
    float4*       md = reinterpret_cast<float4*>(msg + (size_t)d * D);
#pragma unroll
    for (int i = 0; i < 8; i++) {
        float4 v = __ldg(&hs[sub + 16 * i]);
        asm volatile("red.global.add.v4.f32 [%0], {%1,%2,%3,%4};"
                     :: "l"(md + sub + 16 * i),
                        "f"(v.x), "f"(v.y), "f"(v.z), "f"(v.w)
                     : "memory");
    }
}

// ---------------- fused dual GEMM: out = relu(X1@W1 + (X2*inv)@W2 + b) ----------------
// BM=128, BN=128, BK=8, 256 threads, 8x8 micro-tile per thread.
#define BM 128
#define BN 128
#define BK 8

__global__ __launch_bounds__(256) void k_gemm(
    const float* __restrict__ X1, const float* __restrict__ W1,
    const float* __restrict__ X2, const float* __restrict__ W2,
    const float* __restrict__ inv,
    const float* __restrict__ bias,
    float* __restrict__ out)
{
    __shared__ float As[BK][BM];
    __shared__ float Bs[BK][BN];

    const int tid = threadIdx.x;
    const int m0 = blockIdx.y * BM;
    const int n0 = blockIdx.x * BN;

    const int ty = tid >> 4;      // 0..15, micro-row * 8
    const int tx = tid & 15;      // 0..15, micro-col * 8

    // A load map: 256 threads x float4 = 1024 = 128x8 tile
    const int ar = tid >> 1;            // 0..127
    const int akc = (tid & 1) << 2;     // 0 or 4
    const int agr = m0 + ar;
    const bool arow_ok = (agr < N_NODES);
    // B load map: row = tid/32 (0..7), col = (tid%32)*4
    const int br = tid >> 5;
    const int bc = (tid & 31) << 2;

    float acc[8][8];
#pragma unroll
    for (int i = 0; i < 8; i++)
#pragma unroll
        for (int j = 0; j < 8; j++) acc[i][j] = 0.f;

#pragma unroll 1
    for (int phase = 0; phase < 2; phase++) {
        const float* __restrict__ X = phase ? X2 : X1;
        const float* __restrict__ W = phase ? W2 : W1;
        float ascale = 1.0f;
        if (phase) ascale = arow_ok ? __ldg(&inv[agr]) : 0.f;

#pragma unroll 1
        for (int k0 = 0; k0 < D; k0 += BK) {
            // load A tile
            float4 av = make_float4(0.f, 0.f, 0.f, 0.f);
            if (arow_ok)
                av = *reinterpret_cast<const float4*>(&X[(size_t)agr * D + k0 + akc]);
            if (phase) { av.x *= ascale; av.y *= ascale; av.z *= ascale; av.w *= ascale; }
            As[akc + 0][ar] = av.x;
            As[akc + 1][ar] = av.y;
            As[akc + 2][ar] = av.z;
            As[akc + 3][ar] = av.w;
            // load B tile
            float4 bv = *reinterpret_cast<const float4*>(&W[(size_t)(k0 + br) * D + n0 + bc]);
            Bs[br][bc + 0] = bv.x;
            Bs[br][bc + 1] = bv.y;
            Bs[br][bc + 2] = bv.z;
            Bs[br][bc + 3] = bv.w;
            __syncthreads();

#pragma unroll
            for (int k = 0; k < BK; k++) {
                float a[8], b[8];
#pragma unroll
                for (int i = 0; i < 8; i++) a[i] = As[k][ty * 8 + i];
#pragma unroll
                for (int j = 0; j < 8; j++) b[j] = Bs[k][tx * 8 + j];
#pragma unroll
                for (int i = 0; i < 8; i++)
#pragma unroll
                    for (int j = 0; j < 8; j++)
                        acc[i][j] = fmaf(a[i], b[j], acc[i][j]);
            }
            __syncthreads();
        }
    }

    // epilogue: bias + relu, vectorized stores
    float bvals[8];
#pragma unroll
    for (int j = 0; j < 8; j++) bvals[j] = __ldg(&bias[n0 + tx * 8 + j]);

#pragma unroll
    for (int i = 0; i < 8; i++) {
        int gr = m0 + ty * 8 + i;
        if (gr >= N_NODES) continue;
        float4 o0, o1;
        o0.x = fmaxf(acc[i][0] + bvals[0], 0.f);
        o0.y = fmaxf(acc[i][1] + bvals[1], 0.f);
        o0.z = fmaxf(acc[i][2] + bvals[2], 0.f);
        o0.w = fmaxf(acc[i][3] + bvals[3], 0.f);
        o1.x = fmaxf(acc[i][4] + bvals[4], 0.f);
        o1.y = fmaxf(acc[i][5] + bvals[5], 0.f);
        o1.z = fmaxf(acc[i][6] + bvals[6], 0.f);
        o1.w = fmaxf(acc[i][7] + bvals[7], 0.f);
        float* op = &out[(size_t)gr * D + n0 + tx * 8];
        *reinterpret_cast<float4*>(op) = o0;
        *reinterpret_cast<float4*>(op + 4) = o1;
    }
}

// ---------------- launch ----------------
extern "C" void kernel_launch(void* const* d_in, const int* in_sizes, int n_in,
                              void* d_out, int out_size) {
    const int*   in_feat = (const int*)d_in[0];
    const int*   src     = (const int*)d_in[1];
    const int*   dst     = (const int*)d_in[2];
    const float* emb     = (const float*)d_in[3];
    const float* Ws0     = (const float*)d_in[4];
    const float* Wn0     = (const float*)d_in[5];
    const float* b0      = (const float*)d_in[6];
    const float* Ws1     = (const float*)d_in[7];
    const float* Wn1     = (const float*)d_in[8];
    const float* b1      = (const float*)d_in[9];
    float* out = (float*)d_out;

    // symbol addresses (pure lookups, not stream ops — capture-safe)
    float *h0, *msg, *h1, *deg;
    cudaGetSymbolAddress((void**)&h0,  g_h0);
    cudaGetSymbolAddress((void**)&msg, g_msg);
    cudaGetSymbolAddress((void**)&h1,  g_h1);
    cudaGetSymbolAddress((void**)&deg, g_deg);

    cudaMemsetAsync(deg, 0, N_NODES * sizeof(float), 0);
    cudaMemsetAsync(msg, 0, (size_t)N_NODES * D * sizeof(float), 0);

    // h0 = emb[in_feat]
    k_embed<<<(N_NODES * 128 + 255) / 256, 256>>>(in_feat, emb, h0);
    // degree + inverse
    k_deg<<<(N_EDGES + 255) / 256, 256>>>(dst, deg);
    k_inv<<<(N_NODES + 255) / 256, 256>>>(deg);

    dim3 ggrid(D / BN, (N_NODES + BM - 1) / BM);

    // layer 0
    k_scatter<<<N_EDGES / 16, 256>>>(src, dst, h0, msg);
    k_gemm<<<ggrid, 256>>>(h0, Ws0, msg, Wn0, deg, b0, h1);

    // layer 1
    cudaMemsetAsync(msg, 0, (size_t)N_NODES * D * sizeof(float), 0);
    k_scatter<<<N_EDGES / 16, 256>>>(src, dst, h1, msg);
    k_gemm<<<ggrid, 256>>>(h1, Ws1, msg, Wn1, deg, b1, out);
}

// round 3
// speedup vs baseline: 1.9897x; 1.9897x over previous
#include <cuda_runtime.h>
#include <cuda_fp16.h>
#include <cstdint>

#define N_NODES 20000
#define N_EDGES 640000
#define D 512

// ---------------- scratch (no allocs allowed) ----------------
__device__ float g_h0[N_NODES * D];
__device__ float g_msg[N_NODES * D];
__device__ float g_h1[N_NODES * D];
__device__ float g_deg[N_NODES];

// ---------------- embedding lookup ----------------
__global__ void k_embed(const int* __restrict__ type,
                        const float* __restrict__ emb,
                        float* __restrict__ h) {
    int idx = blockIdx.x * blockDim.x + threadIdx.x;
    int n = idx >> 7;
    int j = (idx & 127) << 2;
    if (n < N_NODES) {
        int t = __ldg(&type[n]);
        float4 v = *reinterpret_cast<const float4*>(&emb[(size_t)t * D + j]);
        *reinterpret_cast<float4*>(&h[(size_t)n * D + j]) = v;
    }
}

// ---------------- degree ----------------
__global__ void k_deg(const int* __restrict__ dst, float* __restrict__ deg) {
    int e = blockIdx.x * blockDim.x + threadIdx.x;
    if (e < N_EDGES) atomicAdd(&deg[dst[e]], 1.0f);
}

__global__ void k_inv(float* __restrict__ deg) {
    int i = blockIdx.x * blockDim.x + threadIdx.x;
    if (i < N_NODES) deg[i] = 1.0f / fmaxf(deg[i], 1.0f);
}

// ---------------- edge scatter: msg[dst] += h[src] ----------------
__global__ void k_scatter(const int* __restrict__ src, const int* __restrict__ dst,
                          const float* __restrict__ h, float* __restrict__ msg) {
    int warp = (blockIdx.x * blockDim.x + threadIdx.x) >> 5;
    int lane = threadIdx.x & 31;
    int e = warp * 2 + (lane >> 4);
    int sub = lane & 15;
    if (e >= N_EDGES) return;
    int s = __ldg(&src[e]);
    int d = __ldg(&dst[e]);
    const float4* hs = reinterpret_cast<const float4*>(h + (size_t)s * D);
    float4*       md = reinterpret_cast<float4*>(msg + (size_t)d * D);
#pragma unroll
    for (int i = 0; i < 8; i++) {
        float4 v = __ldg(&hs[sub + 16 * i]);
        asm volatile("red.global.add.v4.f32 [%0], {%1,%2,%3,%4};"
                     :: "l"(md + sub + 16 * i),
                        "f"(v.x), "f"(v.y), "f"(v.z), "f"(v.w)
                     : "memory");
    }
}

// ======================= tensor-core dual GEMM =======================
// out = relu(X1@W1 + (X2*inv)@W2 + bias), fp16x3 split, fp32 accumulate.
// Block tile 128(M) x 128(N) x 16(K). 8 warps: 4(M) x 2(N), warp tile 32x64.

__device__ __forceinline__ uint32_t smem_u32(const void* p) {
    return (uint32_t)__cvta_generic_to_shared(p);
}

__device__ __forceinline__ void ldsm_x4(uint32_t& r0, uint32_t& r1, uint32_t& r2, uint32_t& r3, uint32_t a) {
    asm volatile("ldmatrix.sync.aligned.m8n8.x4.shared.b16 {%0,%1,%2,%3}, [%4];"
                 : "=r"(r0), "=r"(r1), "=r"(r2), "=r"(r3) : "r"(a));
}

__device__ __forceinline__ void ldsm_x4_t(uint32_t& r0, uint32_t& r1, uint32_t& r2, uint32_t& r3, uint32_t a) {
    asm volatile("ldmatrix.sync.aligned.m8n8.x4.trans.shared.b16 {%0,%1,%2,%3}, [%4];"
                 : "=r"(r0), "=r"(r1), "=r"(r2), "=r"(r3) : "r"(a));
}

__device__ __forceinline__ void mma16816(float* c, const uint32_t* a, uint32_t b0, uint32_t b1) {
    asm volatile("mma.sync.aligned.m16n8k16.row.col.f32.f16.f16.f32 "
                 "{%0,%1,%2,%3}, {%4,%5,%6,%7}, {%8,%9}, {%0,%1,%2,%3};"
                 : "+f"(c[0]), "+f"(c[1]), "+f"(c[2]), "+f"(c[3])
                 : "r"(a[0]), "r"(a[1]), "r"(a[2]), "r"(a[3]), "r"(b0), "r"(b1));
}

#define AP 24    // A smem row pitch (halfs), padded
#define BP 136   // B smem row pitch (halfs), padded

__global__ __launch_bounds__(256) void k_gemm(
    const float* __restrict__ X1, const float* __restrict__ W1,
    const float* __restrict__ X2, const float* __restrict__ W2,
    const float* __restrict__ inv,
    const float* __restrict__ bias,
    float* __restrict__ out)
{
    __shared__ __half As1[128][AP], As2[128][AP];
    __shared__ __half Bs1[16][BP],  Bs2[16][BP];

    const int tid  = threadIdx.x;
    const int lane = tid & 31;
    const int wid  = tid >> 5;
    const int wm   = wid >> 1;     // 0..3
    const int wn   = wid & 1;      // 0..1
    const int m0   = blockIdx.y * 128;
    const int n0   = blockIdx.x * 128;

    // global load maps
    const int am  = tid >> 1;              // 0..127 : A row
    const int akq = (tid & 1) << 3;        // 0 or 8 : A k offset (8 floats)
    const int agr = m0 + am;
    const bool arow_ok = (agr < N_NODES);
    const float ainv = arow_ok ? __ldg(&inv[agr]) : 0.f;

    const int bk  = tid >> 5;              // 0..7 : B k rows bk, bk+8
    const int bn  = (tid & 31) << 2;       // B n offset (4 floats)

    // ldmatrix lane addressing
    const int loff8 = lane & 7;
    const int lsel  = (lane >> 3) & 1;
    const int lhi   = (lane >> 4);         // 0 or 1
    const int a_row = wm * 32 + loff8 + lsel * 8;          // + mt*16
    const int a_k   = lhi * 8;
    const int b_k   = loff8 + lsel * 8;
    const int b_n   = wn * 64 + lhi * 8;                   // + ntp*16

    uint32_t adA1[2], adA2[2];
#pragma unroll
    for (int mt = 0; mt < 2; mt++) {
        adA1[mt] = smem_u32(&As1[a_row + mt * 16][a_k]);
        adA2[mt] = smem_u32(&As2[a_row + mt * 16][a_k]);
    }
    uint32_t adB1 = smem_u32(&Bs1[b_k][b_n]);
    uint32_t adB2 = smem_u32(&Bs2[b_k][b_n]);

    float C[2][8][4];
#pragma unroll
    for (int mt = 0; mt < 2; mt++)
#pragma unroll
        for (int nt = 0; nt < 8; nt++)
#pragma unroll
            for (int r = 0; r < 4; r++) C[mt][nt][r] = 0.f;

    const int NIT = 64;   // 2 phases x 32 k-steps of 16
    float4 ra0, ra1, rb0, rb1;

    // prefetch iter 0
    {
        ra0 = ra1 = make_float4(0.f, 0.f, 0.f, 0.f);
        if (arow_ok) {
            ra0 = *reinterpret_cast<const float4*>(&X1[(size_t)agr * D + akq]);
            ra1 = *reinterpret_cast<const float4*>(&X1[(size_t)agr * D + akq + 4]);
        }
        rb0 = *reinterpret_cast<const float4*>(&W1[(size_t)bk * D + n0 + bn]);
        rb1 = *reinterpret_cast<const float4*>(&W1[(size_t)(bk + 8) * D + n0 + bn]);
    }

    for (int it = 0; it < NIT; it++) {
        const int phase = it >> 5;
        const float ascale = phase ? ainv : 1.0f;

        // ---- store prefetched tile to smem (split fp16 hi/lo) ----
        {
            float af[8] = {ra0.x, ra0.y, ra0.z, ra0.w, ra1.x, ra1.y, ra1.z, ra1.w};
            uint4 p1, p2;
            __half* t1 = reinterpret_cast<__half*>(&p1);
            __half* t2 = reinterpret_cast<__half*>(&p2);
#pragma unroll
            for (int j = 0; j < 8; j++) {
                float x = af[j] * ascale;
                __half h = __float2half_rn(x);
                t1[j] = h;
                t2[j] = __float2half_rn(x - __half2float(h));
            }
            *reinterpret_cast<uint4*>(&As1[am][akq]) = p1;
            *reinterpret_cast<uint4*>(&As2[am][akq]) = p2;

            float bf0[4] = {rb0.x, rb0.y, rb0.z, rb0.w};
            float bf1[4] = {rb1.x, rb1.y, rb1.z, rb1.w};
            uint2 q1, q2, q3, q4;
            __half* u1 = reinterpret_cast<__half*>(&q1);
            __half* u2 = reinterpret_cast<__half*>(&q2);
            __half* u3 = reinterpret_cast<__half*>(&q3);
            __half* u4 = reinterpret_cast<__half*>(&q4);
#pragma unroll
            for (int j = 0; j < 4; j++) {
                __half h0 = __float2half_rn(bf0[j]);
                u1[j] = h0;
                u2[j] = __float2half_rn(bf0[j] - __half2float(h0));
                __half h1 = __float2half_rn(bf1[j]);
                u3[j] = h1;
                u4[j] = __float2half_rn(bf1[j] - __half2float(h1));
            }
            *reinterpret_cast<uint2*>(&Bs1[bk][bn])     = q1;
            *reinterpret_cast<uint2*>(&Bs2[bk][bn])     = q2;
            *reinterpret_cast<uint2*>(&Bs1[bk + 8][bn]) = q3;
            *reinterpret_cast<uint2*>(&Bs2[bk + 8][bn]) = q4;
        }
        __syncthreads();

        // ---- prefetch next iter's tile ----
        if (it + 1 < NIT) {
            const int np = (it + 1) >> 5;
            const int k0 = ((it + 1) & 31) << 4;
            const float* X = np ? X2 : X1;
            const float* W = np ? W2 : W1;
            ra0 = ra1 = make_float4(0.f, 0.f, 0.f, 0.f);
            if (arow_ok) {
                ra0 = *reinterpret_cast<const float4*>(&X[(size_t)agr * D + k0 + akq]);
                ra1 = *reinterpret_cast<const float4*>(&X[(size_t)agr * D + k0 + akq + 4]);
            }
            rb0 = *reinterpret_cast<const float4*>(&W[(size_t)(k0 + bk) * D + n0 + bn]);
            rb1 = *reinterpret_cast<const float4*>(&W[(size_t)(k0 + bk + 8) * D + n0 + bn]);
        }

        // ---- fragments + mma (fp16x3: A1B1 + A1B2 + A2B1) ----
        uint32_t A1[2][4], A2[2][4];
#pragma unroll
        for (int mt = 0; mt < 2; mt++) {
            ldsm_x4(A1[mt][0], A1[mt][1], A1[mt][2], A1[mt][3], adA1[mt]);
            ldsm_x4(A2[mt][0], A2[mt][1], A2[mt][2], A2[mt][3], adA2[mt]);
        }
#pragma unroll
        for (int ntp = 0; ntp < 4; ntp++) {
            uint32_t B1[4], B2[4];
            ldsm_x4_t(B1[0], B1[1], B1[2], B1[3], adB1 + ntp * 16 * 2);
            ldsm_x4_t(B2[0], B2[1], B2[2], B2[3], adB2 + ntp * 16 * 2);
#pragma unroll
            for (int mt = 0; mt < 2; mt++) {
                mma16816(C[mt][2 * ntp],     A1[mt], B1[0], B1[1]);
                mma16816(C[mt][2 * ntp + 1], A1[mt], B1[2], B1[3]);
                mma16816(C[mt][2 * ntp],     A1[mt], B2[0], B2[1]);
                mma16816(C[mt][2 * ntp + 1], A1[mt], B2[2], B2[3]);
                mma16816(C[mt][2 * ntp],     A2[mt], B1[0], B1[1]);
                mma16816(C[mt][2 * ntp + 1], A2[mt], B1[2], B1[3]);
            }
        }
        __syncthreads();
    }

    // ---- epilogue: bias + relu, float2 stores ----
#pragma unroll
    for (int nt = 0; nt < 8; nt++) {
        int col = n0 + wn * 64 + nt * 8 + (lane & 3) * 2;
        float bv0 = __ldg(&bias[col]);
        float bv1 = __ldg(&bias[col + 1]);
#pragma unroll
        for (int mt = 0; mt < 2; mt++) {
            int r0 = m0 + wm * 32 + mt * 16 + (lane >> 2);
            if (r0 < N_NODES) {
                float2 v;
                v.x = fmaxf(C[mt][nt][0] + bv0, 0.f);
                v.y = fmaxf(C[mt][nt][1] + bv1, 0.f);
                *reinterpret_cast<float2*>(&out[(size_t)r0 * D + col]) = v;
            }
            int r1 = r0 + 8;
            if (r1 < N_NODES) {
                float2 v;
                v.x = fmaxf(C[mt][nt][2] + bv0, 0.f);
                v.y = fmaxf(C[mt][nt][3] + bv1, 0.f);
                *reinterpret_cast<float2*>(&out[(size_t)r1 * D + col]) = v;
            }
        }
    }
}

// ---------------- launch ----------------
extern "C" void kernel_launch(void* const* d_in, const int* in_sizes, int n_in,
                              void* d_out, int out_size) {
    const int*   in_feat = (const int*)d_in[0];
    const int*   src     = (const int*)d_in[1];
    const int*   dst     = (const int*)d_in[2];
    const float* emb     = (const float*)d_in[3];
    const float* Ws0     = (const float*)d_in[4];
    const float* Wn0     = (const float*)d_in[5];
    const float* b0      = (const float*)d_in[6];
    const float* Ws1     = (const float*)d_in[7];
    const float* Wn1     = (const float*)d_in[8];
    const float* b1      = (const float*)d_in[9];
    float* out = (float*)d_out;

    float *h0, *msg, *h1, *deg;
    cudaGetSymbolAddress((void**)&h0,  g_h0);
    cudaGetSymbolAddress((void**)&msg, g_msg);
    cudaGetSymbolAddress((void**)&h1,  g_h1);
    cudaGetSymbolAddress((void**)&deg, g_deg);

    cudaMemsetAsync(deg, 0, N_NODES * sizeof(float), 0);
    cudaMemsetAsync(msg, 0, (size_t)N_NODES * D * sizeof(float), 0);

    k_embed<<<(N_NODES * 128 + 255) / 256, 256>>>(in_feat, emb, h0);
    k_deg<<<(N_EDGES + 255) / 256, 256>>>(dst, deg);
    k_inv<<<(N_NODES + 255) / 256, 256>>>(deg);

    dim3 ggrid(D / 128, (N_NODES + 127) / 128);

    // layer 0
    k_scatter<<<N_EDGES / 16, 256>>>(src, dst, h0, msg);
    k_gemm<<<ggrid, 256>>>(h0, Ws0, msg, Wn0, deg, b0, h1);

    // layer 1
    cudaMemsetAsync(msg, 0, (size_t)N_NODES * D * sizeof(float), 0);
    k_scatter<<<N_EDGES / 16, 256>>>(src, dst, h1, msg);
    k_gemm<<<ggrid, 256>>>(h1, Ws1, msg, Wn1, deg, b1, out);
}

// round 4
// speedup vs baseline: 2.8618x; 1.4384x over previous
#include <cuda_runtime.h>
#include <cuda_fp16.h>
#include <cstdint>

#define N_NODES 20000
#define N_EDGES 640000
#define D 512

// ---------------- scratch (no allocs allowed) ----------------
__device__ float g_h0[N_NODES * D];
__device__ float g_msg[N_NODES * D];
__device__ float g_h1[N_NODES * D];
__device__ float g_deginv[N_NODES];
__device__ int   g_cnt[N_NODES];
__device__ int   g_cur[N_NODES];
__device__ int   g_rowptr[N_NODES + 1];
__device__ int   g_srcid[N_EDGES];

// ---------------- embedding lookup ----------------
__global__ void k_embed(const int* __restrict__ type,
                        const float* __restrict__ emb,
                        float* __restrict__ h) {
    int idx = blockIdx.x * blockDim.x + threadIdx.x;
    int n = idx >> 7;
    int j = (idx & 127) << 2;
    if (n < N_NODES) {
        int t = __ldg(&type[n]);
        float4 v = *reinterpret_cast<const float4*>(&emb[(size_t)t * D + j]);
        *reinterpret_cast<float4*>(&h[(size_t)n * D + j]) = v;
    }
}

// ---------------- CSR build ----------------
__global__ void k_count(const int* __restrict__ dst, int* __restrict__ cnt) {
    int e = blockIdx.x * blockDim.x + threadIdx.x;
    if (e < N_EDGES) atomicAdd(&cnt[dst[e]], 1);
}

__global__ void k_scan(const int* __restrict__ cnt, int* __restrict__ rowptr) {
    __shared__ int sh[1024];
    __shared__ int running;
    int tid = threadIdx.x;
    if (tid == 0) { running = 0; rowptr[0] = 0; }
    __syncthreads();
    for (int base = 0; base < N_NODES; base += 1024) {
        int x = (base + tid < N_NODES) ? cnt[base + tid] : 0;
        sh[tid] = x;
        __syncthreads();
#pragma unroll
        for (int off = 1; off < 1024; off <<= 1) {
            int v = (tid >= off) ? sh[tid - off] : 0;
            __syncthreads();
            sh[tid] += v;
            __syncthreads();
        }
        if (base + tid < N_NODES) rowptr[base + tid + 1] = running + sh[tid];
        __syncthreads();
        if (tid == 0) running += sh[1023];
        __syncthreads();
    }
}

__global__ void k_inv(const int* __restrict__ cnt, float* __restrict__ deginv) {
    int i = blockIdx.x * blockDim.x + threadIdx.x;
    if (i < N_NODES) deginv[i] = 1.0f / fmaxf((float)cnt[i], 1.0f);
}

__global__ void k_fill(const int* __restrict__ src, const int* __restrict__ dst,
                       const int* __restrict__ rowptr, int* __restrict__ cur,
                       int* __restrict__ srcid) {
    int e = blockIdx.x * blockDim.x + threadIdx.x;
    if (e < N_EDGES) {
        int d = __ldg(&dst[e]);
        int slot = __ldg(&rowptr[d]) + atomicAdd(&cur[d], 1);
        srcid[slot] = __ldg(&src[e]);
    }
}

// ---------------- gather: msg[n] = sum_{s in N(n)} h[s] ----------------
// One 128-thread block per node; each thread owns one float4 column chunk.
__global__ __launch_bounds__(128) void k_gather(
    const int* __restrict__ rowptr, const int* __restrict__ srcid,
    const float* __restrict__ h, float* __restrict__ msg)
{
    const int n   = blockIdx.x;
    const int tid = threadIdx.x;
    const int start = __ldg(&rowptr[n]);
    const int end   = __ldg(&rowptr[n + 1]);

    float4 acc = make_float4(0.f, 0.f, 0.f, 0.f);
    __shared__ int sidx[128];

    for (int base = start; base < end; base += 128) {
        int m = min(128, end - base);
        if (tid < m) sidx[tid] = __ldg(&srcid[base + tid]);
        __syncthreads();
#pragma unroll 4
        for (int j = 0; j < m; j++) {
            int s = sidx[j];
            float4 v = __ldg(reinterpret_cast<const float4*>(h + (size_t)s * D) + tid);
            acc.x += v.x; acc.y += v.y; acc.z += v.z; acc.w += v.w;
        }
        __syncthreads();
    }
    *(reinterpret_cast<float4*>(msg + (size_t)n * D) + tid) = acc;
}

// ======================= tensor-core dual GEMM =======================
// out = relu(X1@W1 + (X2*inv)@W2 + bias), fp16x3 split, fp32 accumulate.
// Block tile 128(M) x 128(N) x 16(K). 8 warps: 4(M) x 2(N), warp tile 32x64.

__device__ __forceinline__ uint32_t smem_u32(const void* p) {
    return (uint32_t)__cvta_generic_to_shared(p);
}

__device__ __forceinline__ void ldsm_x4(uint32_t& r0, uint32_t& r1, uint32_t& r2, uint32_t& r3, uint32_t a) {
    asm volatile("ldmatrix.sync.aligned.m8n8.x4.shared.b16 {%0,%1,%2,%3}, [%4];"
                 : "=r"(r0), "=r"(r1), "=r"(r2), "=r"(r3) : "r"(a));
}

__device__ __forceinline__ void ldsm_x4_t(uint32_t& r0, uint32_t& r1, uint32_t& r2, uint32_t& r3, uint32_t a) {
    asm volatile("ldmatrix.sync.aligned.m8n8.x4.trans.shared.b16 {%0,%1,%2,%3}, [%4];"
                 : "=r"(r0), "=r"(r1), "=r"(r2), "=r"(r3) : "r"(a));
}

__device__ __forceinline__ void mma16816(float* c, const uint32_t* a, uint32_t b0, uint32_t b1) {
    asm volatile("mma.sync.aligned.m16n8k16.row.col.f32.f16.f16.f32 "
                 "{%0,%1,%2,%3}, {%4,%5,%6,%7}, {%8,%9}, {%0,%1,%2,%3};"
                 : "+f"(c[0]), "+f"(c[1]), "+f"(c[2]), "+f"(c[3])
                 : "r"(a[0]), "r"(a[1]), "r"(a[2]), "r"(a[3]), "r"(b0), "r"(b1));
}

#define AP 24    // A smem row pitch (halfs), padded
#define BP 136   // B smem row pitch (halfs), padded

__global__ __launch_bounds__(256) void k_gemm(
    const float* __restrict__ X1, const float* __restrict__ W1,
    const float* __restrict__ X2, const float* __restrict__ W2,
    const float* __restrict__ inv,
    const float* __restrict__ bias,
    float* __restrict__ out)
{
    __shared__ __half As1[128][AP], As2[128][AP];
    __shared__ __half Bs1[16][BP],  Bs2[16][BP];

    const int tid  = threadIdx.x;
    const int lane = tid & 31;
    const int wid  = tid >> 5;
    const int wm   = wid >> 1;     // 0..3
    const int wn   = wid & 1;      // 0..1
    const int m0   = blockIdx.y * 128;
    const int n0   = blockIdx.x * 128;

    // global load maps
    const int am  = tid >> 1;              // 0..127 : A row
    const int akq = (tid & 1) << 3;        // 0 or 8 : A k offset (8 floats)
    const int agr = m0 + am;
    const bool arow_ok = (agr < N_NODES);
    const float ainv = arow_ok ? __ldg(&inv[agr]) : 0.f;

    const int bk  = tid >> 5;              // 0..7 : B k rows bk, bk+8
    const int bn  = (tid & 31) << 2;       // B n offset (4 floats)

    // ldmatrix lane addressing
    const int loff8 = lane & 7;
    const int lsel  = (lane >> 3) & 1;
    const int lhi   = (lane >> 4);         // 0 or 1
    const int a_row = wm * 32 + loff8 + lsel * 8;          // + mt*16
    const int a_k   = lhi * 8;
    const int b_k   = loff8 + lsel * 8;
    const int b_n   = wn * 64 + lhi * 8;                   // + ntp*16

    uint32_t adA1[2], adA2[2];
#pragma unroll
    for (int mt = 0; mt < 2; mt++) {
        adA1[mt] = smem_u32(&As1[a_row + mt * 16][a_k]);
        adA2[mt] = smem_u32(&As2[a_row + mt * 16][a_k]);
    }
    uint32_t adB1 = smem_u32(&Bs1[b_k][b_n]);
    uint32_t adB2 = smem_u32(&Bs2[b_k][b_n]);

    float C[2][8][4];
#pragma unroll
    for (int mt = 0; mt < 2; mt++)
#pragma unroll
        for (int nt = 0; nt < 8; nt++)
#pragma unroll
            for (int r = 0; r < 4; r++) C[mt][nt][r] = 0.f;

    const int NIT = 64;   // 2 phases x 32 k-steps of 16
    float4 ra0, ra1, rb0, rb1;

    // prefetch iter 0
    {
        ra0 = ra1 = make_float4(0.f, 0.f, 0.f, 0.f);
        if (arow_ok) {
            ra0 = *reinterpret_cast<const float4*>(&X1[(size_t)agr * D + akq]);
            ra1 = *reinterpret_cast<const float4*>(&X1[(size_t)agr * D + akq + 4]);
        }
        rb0 = *reinterpret_cast<const float4*>(&W1[(size_t)bk * D + n0 + bn]);
        rb1 = *reinterpret_cast<const float4*>(&W1[(size_t)(bk + 8) * D + n0 + bn]);
    }

    for (int it = 0; it < NIT; it++) {
        const int phase = it >> 5;
        const float ascale = phase ? ainv : 1.0f;

        // ---- store prefetched tile to smem (split fp16 hi/lo) ----
        {
            float af[8] = {ra0.x, ra0.y, ra0.z, ra0.w, ra1.x, ra1.y, ra1.z, ra1.w};
            uint4 p1, p2;
            __half* t1 = reinterpret_cast<__half*>(&p1);
            __half* t2 = reinterpret_cast<__half*>(&p2);
#pragma unroll
            for (int j = 0; j < 8; j++) {
                float x = af[j] * ascale;
                __half h = __float2half_rn(x);
                t1[j] = h;
                t2[j] = __float2half_rn(x - __half2float(h));
            }
            *reinterpret_cast<uint4*>(&As1[am][akq]) = p1;
            *reinterpret_cast<uint4*>(&As2[am][akq]) = p2;

            float bf0[4] = {rb0.x, rb0.y, rb0.z, rb0.w};
            float bf1[4] = {rb1.x, rb1.y, rb1.z, rb1.w};
            uint2 q1, q2, q3, q4;
            __half* u1 = reinterpret_cast<__half*>(&q1);
            __half* u2 = reinterpret_cast<__half*>(&q2);
            __half* u3 = reinterpret_cast<__half*>(&q3);
            __half* u4 = reinterpret_cast<__half*>(&q4);
#pragma unroll
            for (int j = 0; j < 4; j++) {
                __half h0 = __float2half_rn(bf0[j]);
                u1[j] = h0;
                u2[j] = __float2half_rn(bf0[j] - __half2float(h0));
                __half h1 = __float2half_rn(bf1[j]);
                u3[j] = h1;
                u4[j] = __float2half_rn(bf1[j] - __half2float(h1));
            }
            *reinterpret_cast<uint2*>(&Bs1[bk][bn])     = q1;
            *reinterpret_cast<uint2*>(&Bs2[bk][bn])     = q2;
            *reinterpret_cast<uint2*>(&Bs1[bk + 8][bn]) = q3;
            *reinterpret_cast<uint2*>(&Bs2[bk + 8][bn]) = q4;
        }
        __syncthreads();

        // ---- prefetch next iter's tile ----
        if (it + 1 < NIT) {
            const int np = (it + 1) >> 5;
            const int k0 = ((it + 1) & 31) << 4;
            const float* X = np ? X2 : X1;
            const float* W = np ? W2 : W1;
            ra0 = ra1 = make_float4(0.f, 0.f, 0.f, 0.f);
            if (arow_ok) {
                ra0 = *reinterpret_cast<const float4*>(&X[(size_t)agr * D + k0 + akq]);
                ra1 = *reinterpret_cast<const float4*>(&X[(size_t)agr * D + k0 + akq + 4]);
            }
            rb0 = *reinterpret_cast<const float4*>(&W[(size_t)(k0 + bk) * D + n0 + bn]);
            rb1 = *reinterpret_cast<const float4*>(&W[(size_t)(k0 + bk + 8) * D + n0 + bn]);
        }

        // ---- fragments + mma (fp16x3: A1B1 + A1B2 + A2B1) ----
        uint32_t A1[2][4], A2[2][4];
#pragma unroll
        for (int mt = 0; mt < 2; mt++) {
            ldsm_x4(A1[mt][0], A1[mt][1], A1[mt][2], A1[mt][3], adA1[mt]);
            ldsm_x4(A2[mt][0], A2[mt][1], A2[mt][2], A2[mt][3], adA2[mt]);
        }
#pragma unroll
        for (int ntp = 0; ntp < 4; ntp++) {
            uint32_t B1[4], B2[4];
            ldsm_x4_t(B1[0], B1[1], B1[2], B1[3], adB1 + ntp * 16 * 2);
            ldsm_x4_t(B2[0], B2[1], B2[2], B2[3], adB2 + ntp * 16 * 2);
#pragma unroll
            for (int mt = 0; mt < 2; mt++) {
                mma16816(C[mt][2 * ntp],     A1[mt], B1[0], B1[1]);
                mma16816(C[mt][2 * ntp + 1], A1[mt], B1[2], B1[3]);
                mma16816(C[mt][2 * ntp],     A1[mt], B2[0], B2[1]);
                mma16816(C[mt][2 * ntp + 1], A1[mt], B2[2], B2[3]);
                mma16816(C[mt][2 * ntp],     A2[mt], B1[0], B1[1]);
                mma16816(C[mt][2 * ntp + 1], A2[mt], B1[2], B1[3]);
            }
        }
        __syncthreads();
    }

    // ---- epilogue: bias + relu, float2 stores ----
#pragma unroll
    for (int nt = 0; nt < 8; nt++) {
        int col = n0 + wn * 64 + nt * 8 + (lane & 3) * 2;
        float bv0 = __ldg(&bias[col]);
        float bv1 = __ldg(&bias[col + 1]);
#pragma unroll
        for (int mt = 0; mt < 2; mt++) {
            int r0 = m0 + wm * 32 + mt * 16 + (lane >> 2);
            if (r0 < N_NODES) {
                float2 v;
                v.x = fmaxf(C[mt][nt][0] + bv0, 0.f);
                v.y = fmaxf(C[mt][nt][1] + bv1, 0.f);
                *reinterpret_cast<float2*>(&out[(size_t)r0 * D + col]) = v;
            }
            int r1 = r0 + 8;
            if (r1 < N_NODES) {
                float2 v;
                v.x = fmaxf(C[mt][nt][2] + bv0, 0.f);
                v.y = fmaxf(C[mt][nt][3] + bv1, 0.f);
                *reinterpret_cast<float2*>(&out[(size_t)r1 * D + col]) = v;
            }
        }
    }
}

// ---------------- launch ----------------
extern "C" void kernel_launch(void* const* d_in, const int* in_sizes, int n_in,
                              void* d_out, int out_size) {
    const int*   in_feat = (const int*)d_in[0];
    const int*   src     = (const int*)d_in[1];
    const int*   dst     = (const int*)d_in[2];
    const float* emb     = (const float*)d_in[3];
    const float* Ws0     = (const float*)d_in[4];
    const float* Wn0     = (const float*)d_in[5];
    const float* b0      = (const float*)d_in[6];
    const float* Ws1     = (const float*)d_in[7];
    const float* Wn1     = (const float*)d_in[8];
    const float* b1      = (const float*)d_in[9];
    float* out = (float*)d_out;

    float *h0, *msg, *h1, *deginv;
    int *cnt, *cur, *rowptr, *srcid;
    cudaGetSymbolAddress((void**)&h0,     g_h0);
    cudaGetSymbolAddress((void**)&msg,    g_msg);
    cudaGetSymbolAddress((void**)&h1,     g_h1);
    cudaGetSymbolAddress((void**)&deginv, g_deginv);
    cudaGetSymbolAddress((void**)&cnt,    g_cnt);
    cudaGetSymbolAddress((void**)&cur,    g_cur);
    cudaGetSymbolAddress((void**)&rowptr, g_rowptr);
    cudaGetSymbolAddress((void**)&srcid,  g_srcid);

    cudaMemsetAsync(cnt, 0, N_NODES * sizeof(int), 0);
    cudaMemsetAsync(cur, 0, N_NODES * sizeof(int), 0);

    // h0 = emb[in_feat]
    k_embed<<<(N_NODES * 128 + 255) / 256, 256>>>(in_feat, emb, h0);

    // CSR build (reused by both layers)
    k_count<<<(N_EDGES + 255) / 256, 256>>>(dst, cnt);
    k_scan<<<1, 1024>>>(cnt, rowptr);
    k_inv<<<(N_NODES + 255) / 256, 256>>>(cnt, deginv);
    k_fill<<<(N_EDGES + 255) / 256, 256>>>(src, dst, rowptr, cur, srcid);

    dim3 ggrid(D / 128, (N_NODES + 127) / 128);

    // layer 0
    k_gather<<<N_NODES, 128>>>(rowptr, srcid, h0, msg);
    k_gemm<<<ggrid, 256>>>(h0, Ws0, msg, Wn0, deginv, b0, h1);

    // layer 1
    k_gather<<<N_NODES, 128>>>(rowptr, srcid, h1, msg);
    k_gemm<<<ggrid, 256>>>(h1, Ws1, msg, Wn1, deginv, b1, out);
}